// round 4
// baseline (speedup 1.0000x reference)
#include <cuda_runtime.h>
#include <math.h>

#define BB 4
#define SS 1024
#define DD 1024
#define HH 16
#define DKK 64

// Scratch (no allocations allowed) — head-major QKV + attention output.
__device__ float g_q[BB * HH * SS * DKK];
__device__ float g_k[BB * HH * SS * DKK];
__device__ float g_v[BB * HH * SS * DKK];
__device__ float g_x[BB * SS * DD];

// ---------------------------------------------------------------------------
// NT SGEMM: C[m,n] = sum_k A[m,k] * W[n,k] + bias[n]
// M=4096, N=1024, K=1024. BM=BN=128, BK=16, 256 threads, 8x8 per thread.
// DST 0/1/2: epilogue scatters into g_q/g_k/g_v as [B,H,S,DK].
// DST 3:     A is g_x (ignores A param), plain row-major write to C.
// ---------------------------------------------------------------------------
template <int DST>
__global__ __launch_bounds__(256) void gemm_nt(const float* __restrict__ A,
                                               const float* __restrict__ W,
                                               const float* __restrict__ bias,
                                               float* __restrict__ C) {
    __shared__ float As[16][128];
    __shared__ float Bs[16][128];
    const int K = DD;
    const int tid = threadIdx.x;
    const int m0 = blockIdx.y * 128;
    const int n0 = blockIdx.x * 128;
    const int lr = tid >> 2;          // 0..63 (row within half-tile)
    const int lc = (tid & 3) << 2;    // 0,4,8,12 (k-col)
    const int ty = tid >> 4;          // 0..15
    const int tx = tid & 15;          // 0..15

    if (DST == 3) A = g_x;

    float acc[8][8];
#pragma unroll
    for (int i = 0; i < 8; i++)
#pragma unroll
        for (int j = 0; j < 8; j++) acc[i][j] = 0.f;

    const float* Ap = A + (size_t)(m0 + lr) * K + lc;
    const float* Wp = W + (size_t)(n0 + lr) * K + lc;

    for (int k0 = 0; k0 < K; k0 += 16) {
#pragma unroll
        for (int i = 0; i < 2; i++) {
            float4 a = *(const float4*)(Ap + (size_t)(i * 64) * K + k0);
            As[lc + 0][lr + i * 64] = a.x;
            As[lc + 1][lr + i * 64] = a.y;
            As[lc + 2][lr + i * 64] = a.z;
            As[lc + 3][lr + i * 64] = a.w;
            float4 w = *(const float4*)(Wp + (size_t)(i * 64) * K + k0);
            Bs[lc + 0][lr + i * 64] = w.x;
            Bs[lc + 1][lr + i * 64] = w.y;
            Bs[lc + 2][lr + i * 64] = w.z;
            Bs[lc + 3][lr + i * 64] = w.w;
        }
        __syncthreads();
#pragma unroll
        for (int k = 0; k < 16; k++) {
            float a[8], b[8];
            *(float4*)(a)     = *(const float4*)&As[k][ty * 8];
            *(float4*)(a + 4) = *(const float4*)&As[k][ty * 8 + 4];
            *(float4*)(b)     = *(const float4*)&Bs[k][tx * 8];
            *(float4*)(b + 4) = *(const float4*)&Bs[k][tx * 8 + 4];
#pragma unroll
            for (int i = 0; i < 8; i++)
#pragma unroll
                for (int j = 0; j < 8; j++) acc[i][j] += a[i] * b[j];
        }
        __syncthreads();
    }

#pragma unroll
    for (int i = 0; i < 8; i++) {
        const int m = m0 + ty * 8 + i;
#pragma unroll
        for (int j = 0; j < 8; j++) {
            const int n = n0 + tx * 8 + j;
            float v = acc[i][j] + __ldg(&bias[n]);
            if (DST == 3) {
                C[(size_t)m * DD + n] = v;
            } else {
                const int bb = m >> 10;          // m / S
                const int s  = m & (SS - 1);
                const int h  = n >> 6;           // n / DK
                const int dk = n & (DKK - 1);
                float* dst = (DST == 0) ? g_q : (DST == 1) ? g_k : g_v;
                dst[(((size_t)(bb * HH + h)) * SS + s) * DKK + dk] = v;
            }
        }
    }
}

// ---------------------------------------------------------------------------
// Flash-style attention. Grid: (S/64, B*H). 256 threads.
// CTA handles 64 q-rows of one (b,h); loops over 16 k-tiles of 64.
// Q,K stored d-major (transposed, pitch 68 = 272B, 16B-aligned rows) in SMEM
// -> aligned, conflict-light LDS.128 in the score loop. V row-major (pitch 68).
// P tile 64x64. Online softmax; fully-masked rows degrade to uniform softmax
// exactly like the reference (-1e9 fill).
// ---------------------------------------------------------------------------
#define PIT 68

__global__ __launch_bounds__(256) void attn_kernel(const int* __restrict__ mask) {
    extern __shared__ float sm[];
    float* Qt = sm;               // [64 d][PIT] : Qt[d][row]
    float* Kt = Qt + 64 * PIT;    // [64 d][PIT] : Kt[d][row]
    float* Vs = Kt + 64 * PIT;    // [64 row][PIT] : Vs[row][d]
    float* Ps = Vs + 64 * PIT;    // [64][64]

    const int tid = threadIdx.x;
    const int bh  = blockIdx.y;        // 0..63
    const int b   = bh >> 4;
    const int h   = bh & 15;
    const int q0  = blockIdx.x * 64;

    const float* qg = g_q + ((size_t)bh * SS + q0) * DKK;
    const float* kg = g_k + (size_t)bh * SS * DKK;
    const float* vg = g_v + (size_t)bh * SS * DKK;

    // Load Q tile (4096 contiguous floats), store transposed.
#pragma unroll
    for (int u = 0; u < 4; u++) {
        int off = tid + u * 256;                 // float4 index
        float4 qv = *(const float4*)(qg + (size_t)off * 4);
        int row = off >> 4;
        int col = (off & 15) * 4;
        Qt[(col + 0) * PIT + row] = qv.x;
        Qt[(col + 1) * PIT + row] = qv.y;
        Qt[(col + 2) * PIT + row] = qv.z;
        Qt[(col + 3) * PIT + row] = qv.w;
    }

    const int ty = tid >> 4, tx = tid & 15;
    float m_i[4], l_i[4], acc[4][4];
#pragma unroll
    for (int r = 0; r < 4; r++) {
        m_i[r] = -1e30f;
        l_i[r] = 0.f;
#pragma unroll
        for (int j = 0; j < 4; j++) acc[r][j] = 0.f;
    }

    for (int kt = 0; kt < SS; kt += 64) {
        __syncthreads();  // protects Q (iter 0) and K/V/P reuse (iter >0)
#pragma unroll
        for (int u = 0; u < 4; u++) {
            int off = tid + u * 256;
            int row = off >> 4;
            int col = (off & 15) * 4;
            float4 kv = *(const float4*)(kg + (size_t)kt * DKK + (size_t)off * 4);
            Kt[(col + 0) * PIT + row] = kv.x;
            Kt[(col + 1) * PIT + row] = kv.y;
            Kt[(col + 2) * PIT + row] = kv.z;
            Kt[(col + 3) * PIT + row] = kv.w;
            float4 vv = *(const float4*)(vg + (size_t)kt * DKK + (size_t)off * 4);
            *(float4*)&Vs[row * PIT + col] = vv;
        }
        __syncthreads();

        // Scores: s[r][c] = sum_d Q[qr][d] * K[kc][d]
        float s[4][4];
#pragma unroll
        for (int r = 0; r < 4; r++)
#pragma unroll
            for (int c = 0; c < 4; c++) s[r][c] = 0.f;

#pragma unroll 16
        for (int d = 0; d < DKK; d++) {
            float4 q4 = *(const float4*)&Qt[d * PIT + ty * 4];
            float4 k4 = *(const float4*)&Kt[d * PIT + tx * 4];
            float qa[4] = {q4.x, q4.y, q4.z, q4.w};
            float ka[4] = {k4.x, k4.y, k4.z, k4.w};
#pragma unroll
            for (int r = 0; r < 4; r++)
#pragma unroll
                for (int c = 0; c < 4; c++) s[r][c] += qa[r] * ka[c];
        }

        // Scale + mask (-1e9 where mask==0), mask read straight from gmem.
        const int* mptr = mask + ((size_t)b * SS + (q0 + ty * 4)) * SS + kt + tx * 4;
#pragma unroll
        for (int r = 0; r < 4; r++)
#pragma unroll
            for (int c = 0; c < 4; c++) {
                int mv = __ldg(mptr + (size_t)r * SS + c);
                s[r][c] = mv ? s[r][c] * 0.125f : -1e9f;
            }

        // Online softmax update (row groups = 16 lanes, shfl width 16).
#pragma unroll
        for (int r = 0; r < 4; r++) {
            float mx = fmaxf(fmaxf(s[r][0], s[r][1]), fmaxf(s[r][2], s[r][3]));
#pragma unroll
            for (int o = 8; o > 0; o >>= 1)
                mx = fmaxf(mx, __shfl_xor_sync(0xffffffffu, mx, o, 16));
            float mnew = fmaxf(m_i[r], mx);
            float corr = __expf(m_i[r] - mnew);
            m_i[r] = mnew;
            float p0 = __expf(s[r][0] - mnew);
            float p1 = __expf(s[r][1] - mnew);
            float p2 = __expf(s[r][2] - mnew);
            float p3 = __expf(s[r][3] - mnew);
            *(float4*)&Ps[(ty * 4 + r) * 64 + tx * 4] = make_float4(p0, p1, p2, p3);
            float rs = p0 + p1 + p2 + p3;
#pragma unroll
            for (int o = 8; o > 0; o >>= 1)
                rs += __shfl_xor_sync(0xffffffffu, rs, o, 16);
            l_i[r] = l_i[r] * corr + rs;
#pragma unroll
            for (int j = 0; j < 4; j++) acc[r][j] *= corr;
        }
        __syncthreads();

        // O += P @ V   (acc[r][j] covers dims tx*4+j)
#pragma unroll 4
        for (int c = 0; c < 64; c += 4) {
            float4 v0 = *(const float4*)&Vs[(c + 0) * PIT + tx * 4];
            float4 v1 = *(const float4*)&Vs[(c + 1) * PIT + tx * 4];
            float4 v2 = *(const float4*)&Vs[(c + 2) * PIT + tx * 4];
            float4 v3 = *(const float4*)&Vs[(c + 3) * PIT + tx * 4];
#pragma unroll
            for (int r = 0; r < 4; r++) {
                float4 p4 = *(const float4*)&Ps[(ty * 4 + r) * 64 + c];
                acc[r][0] += p4.x * v0.x + p4.y * v1.x + p4.z * v2.x + p4.w * v3.x;
                acc[r][1] += p4.x * v0.y + p4.y * v1.y + p4.z * v2.y + p4.w * v3.y;
                acc[r][2] += p4.x * v0.z + p4.y * v1.z + p4.z * v2.z + p4.w * v3.z;
                acc[r][3] += p4.x * v0.w + p4.y * v1.w + p4.z * v2.w + p4.w * v3.w;
            }
        }
    }

    // Normalize, write to g_x[b][s][h*64+d]
#pragma unroll
    for (int r = 0; r < 4; r++) {
        float inv = 1.f / l_i[r];
        float4 o = make_float4(acc[r][0] * inv, acc[r][1] * inv,
                               acc[r][2] * inv, acc[r][3] * inv);
        size_t dst = ((size_t)(b * SS + q0 + ty * 4 + r)) * DD + h * 64 + tx * 4;
        *(float4*)&g_x[dst] = o;
    }
}

// ---------------------------------------------------------------------------
extern "C" void kernel_launch(void* const* d_in, const int* in_sizes, int n_in,
                              void* d_out, int out_size) {
    const float* query = (const float*)d_in[0];
    const float* key   = (const float*)d_in[1];
    const float* value = (const float*)d_in[2];
    const int*   mask  = (const int*)d_in[3];
    const float* wq = (const float*)d_in[4];
    const float* bq = (const float*)d_in[5];
    const float* wk = (const float*)d_in[6];
    const float* bk = (const float*)d_in[7];
    const float* wv = (const float*)d_in[8];
    const float* bv = (const float*)d_in[9];
    const float* wo = (const float*)d_in[10];
    const float* bo = (const float*)d_in[11];
    float* out = (float*)d_out;

    // One-time SMEM opt-in (host-side attribute, not a stream op; idempotent).
    static int smem_ok = 0;
    const int attn_smem = (3 * 64 * PIT + 64 * 64) * (int)sizeof(float);  // 68608 B
    if (!smem_ok) {
        cudaFuncSetAttribute(attn_kernel, cudaFuncAttributeMaxDynamicSharedMemorySize,
                             attn_smem);
        smem_ok = 1;
    }

    dim3 ggrid(DD / 128, (BB * SS) / 128);  // (8, 32)
    gemm_nt<0><<<ggrid, 256>>>(query, wq, bq, nullptr);
    gemm_nt<1><<<ggrid, 256>>>(key,   wk, bk, nullptr);
    gemm_nt<2><<<ggrid, 256>>>(value, wv, bv, nullptr);

    attn_kernel<<<dim3(SS / 64, BB * HH), 256, attn_smem>>>(mask);

    gemm_nt<3><<<ggrid, 256>>>(nullptr, wo, bo, out);
}

// round 5
// speedup vs baseline: 1.4025x; 1.4025x over previous
#include <cuda_runtime.h>
#include <math.h>
#include <stdint.h>

#define BB 4
#define SS 1024
#define DD 1024
#define HH 16
#define DKK 64

// Scratch (no allocations allowed) — head-major QKV + attention output.
__device__ float g_q[BB * HH * SS * DKK];
__device__ float g_k[BB * HH * SS * DKK];
__device__ float g_v[BB * HH * SS * DKK];
__device__ float g_x[BB * SS * DD];

__device__ __forceinline__ uint32_t f2tf32(float x) {
    uint32_t r;
    asm("cvt.rna.tf32.f32 %0, %1;" : "=r"(r) : "f"(x));
    return r;
}

__device__ __forceinline__ void mma_tf32(float& c0, float& c1, float& c2, float& c3,
                                         uint32_t a0, uint32_t a1, uint32_t a2, uint32_t a3,
                                         uint32_t b0, uint32_t b1) {
    asm volatile(
        "mma.sync.aligned.m16n8k8.row.col.f32.tf32.tf32.f32 "
        "{%0,%1,%2,%3}, {%4,%5,%6,%7}, {%8,%9}, {%0,%1,%2,%3};"
        : "+f"(c0), "+f"(c1), "+f"(c2), "+f"(c3)
        : "r"(a0), "r"(a1), "r"(a2), "r"(a3), "r"(b0), "r"(b1));
}

// ---------------------------------------------------------------------------
// NT tensor-core GEMM (tf32): C[m,n] = sum_k A[m,k]*W[n,k] + bias[n]
// M=4096, N=1024, K=1024. BM=BN=128, BK=16, 256 thr = 8 warps (2m x 4n),
// warp tile 64x32 via mma.m16n8k8. Double-buffered SMEM, register prefetch,
// cvt.rna.tf32 on the store path. SMEM k-layout pair-interleaved:
// within each 8-k group, position = 2*(k%4) + k/4, so a thread's (k=t, k=t+4)
// fragment pair is one aligned 64-bit LDS. Row pad = 20 floats.
// DST 0/1/2 scatter into g_q/g_k/g_v as [B,H,S,DK]; DST 3 row-major to C.
// ---------------------------------------------------------------------------
#define GPAD 20

template <int DST>
__global__ __launch_bounds__(256) void gemm_tc(const float* __restrict__ A,
                                               const float* __restrict__ W,
                                               const float* __restrict__ bias,
                                               float* __restrict__ C) {
    __shared__ uint32_t As[2][128 * GPAD];
    __shared__ uint32_t Bs[2][128 * GPAD];

    const int tid  = threadIdx.x;
    const int lane = tid & 31;
    const int warp = tid >> 5;
    const int wm   = warp >> 2;      // 0..1
    const int wn   = warp & 3;       // 0..3
    const int g    = lane >> 2;      // 0..7
    const int t    = lane & 3;       // 0..3
    const int m0 = blockIdx.y * 128;
    const int n0 = blockIdx.x * 128;

    if (DST == 3) A = g_x;

    // Global load assignment: 2 threads per row, 8 floats each.
    const int lrow  = tid >> 1;           // 0..127
    const int khalf = (tid & 1) * 8;      // 0 or 8
    const float* Ap = A + (size_t)(m0 + lrow) * DD + khalf;
    const float* Wp = W + (size_t)(n0 + lrow) * DD + khalf;
    const int sbase = lrow * GPAD + khalf;

    float acc[4][4][4];
#pragma unroll
    for (int i = 0; i < 4; i++)
#pragma unroll
        for (int j = 0; j < 4; j++)
#pragma unroll
            for (int c = 0; c < 4; c++) acc[i][j][c] = 0.f;

    // Prefetch tile 0.
    float4 ra0 = *(const float4*)(Ap);
    float4 ra1 = *(const float4*)(Ap + 4);
    float4 rb0 = *(const float4*)(Wp);
    float4 rb1 = *(const float4*)(Wp + 4);

    // Store permuted+converted: v0 = k 0..3 -> pos 0,2,4,6 ; v1 = k 4..7 -> 1,3,5,7
    auto sts_tile = [&](uint32_t* SA, uint32_t* SB,
                        float4 a0, float4 a1, float4 b0, float4 b1) {
        SA[sbase + 0] = f2tf32(a0.x); SA[sbase + 2] = f2tf32(a0.y);
        SA[sbase + 4] = f2tf32(a0.z); SA[sbase + 6] = f2tf32(a0.w);
        SA[sbase + 1] = f2tf32(a1.x); SA[sbase + 3] = f2tf32(a1.y);
        SA[sbase + 5] = f2tf32(a1.z); SA[sbase + 7] = f2tf32(a1.w);
        SB[sbase + 0] = f2tf32(b0.x); SB[sbase + 2] = f2tf32(b0.y);
        SB[sbase + 4] = f2tf32(b0.z); SB[sbase + 6] = f2tf32(b0.w);
        SB[sbase + 1] = f2tf32(b1.x); SB[sbase + 3] = f2tf32(b1.y);
        SB[sbase + 5] = f2tf32(b1.z); SB[sbase + 7] = f2tf32(b1.w);
    };

    sts_tile(As[0], Bs[0], ra0, ra1, rb0, rb1);
    __syncthreads();

    int cur = 0;
    const int NTILES = DD / 16;  // 64
    for (int it = 0; it < NTILES; ++it) {
        // Prefetch next tile into registers (overlaps with compute below).
        if (it + 1 < NTILES) {
            const float* ap = Ap + (it + 1) * 16;
            const float* wp = Wp + (it + 1) * 16;
            ra0 = *(const float4*)(ap);
            ra1 = *(const float4*)(ap + 4);
            rb0 = *(const float4*)(wp);
            rb1 = *(const float4*)(wp + 4);
        }

        // Compute current tile: 2 k-steps of 8.
        const uint32_t* SA = As[cur];
        const uint32_t* SB = Bs[cur];
#pragma unroll
        for (int s = 0; s < 2; s++) {
            uint32_t a[4][4];
#pragma unroll
            for (int mi = 0; mi < 4; mi++) {
                const int r0 = wm * 64 + mi * 16 + g;
                uint2 p0 = *(const uint2*)&SA[r0 * GPAD + s * 8 + 2 * t];
                uint2 p1 = *(const uint2*)&SA[(r0 + 8) * GPAD + s * 8 + 2 * t];
                a[mi][0] = p0.x; a[mi][1] = p1.x; a[mi][2] = p0.y; a[mi][3] = p1.y;
            }
            uint32_t b[4][2];
#pragma unroll
            for (int nj = 0; nj < 4; nj++) {
                uint2 q = *(const uint2*)&SB[(wn * 32 + nj * 8 + g) * GPAD + s * 8 + 2 * t];
                b[nj][0] = q.x; b[nj][1] = q.y;
            }
#pragma unroll
            for (int mi = 0; mi < 4; mi++)
#pragma unroll
                for (int nj = 0; nj < 4; nj++)
                    mma_tf32(acc[mi][nj][0], acc[mi][nj][1], acc[mi][nj][2], acc[mi][nj][3],
                             a[mi][0], a[mi][1], a[mi][2], a[mi][3],
                             b[nj][0], b[nj][1]);
        }

        if (it + 1 < NTILES) {
            sts_tile(As[cur ^ 1], Bs[cur ^ 1], ra0, ra1, rb0, rb1);
            __syncthreads();
            cur ^= 1;
        }
    }

    // Epilogue: c0=C[g][2t], c1=C[g][2t+1], c2=C[g+8][2t], c3=C[g+8][2t+1]
#pragma unroll
    for (int mi = 0; mi < 4; mi++) {
#pragma unroll
        for (int nj = 0; nj < 4; nj++) {
            const int n = n0 + wn * 32 + nj * 8 + 2 * t;
            const float bn0 = __ldg(&bias[n]);
            const float bn1 = __ldg(&bias[n + 1]);
#pragma unroll
            for (int rr = 0; rr < 2; rr++) {
                const int m = m0 + wm * 64 + mi * 16 + g + rr * 8;
                const float v0 = acc[mi][nj][rr * 2 + 0] + bn0;
                const float v1 = acc[mi][nj][rr * 2 + 1] + bn1;
                if (DST == 3) {
                    *(float2*)&C[(size_t)m * DD + n] = make_float2(v0, v1);
                } else {
                    const int bb = m >> 10;
                    const int s  = m & (SS - 1);
                    const int h  = n >> 6;
                    const int dk = n & (DKK - 1);
                    float* dst = (DST == 0) ? g_q : (DST == 1) ? g_k : g_v;
                    *(float2*)&dst[(((size_t)(bb * HH + h)) * SS + s) * DKK + dk] =
                        make_float2(v0, v1);
                }
            }
        }
    }
}

// ---------------------------------------------------------------------------
// Flash-style attention (unchanged from R4 baseline). Grid: (S/64, B*H), 256 thr.
// ---------------------------------------------------------------------------
#define PIT 68

__global__ __launch_bounds__(256) void attn_kernel(const int* __restrict__ mask) {
    extern __shared__ float sm[];
    float* Qt = sm;               // [64 d][PIT]
    float* Kt = Qt + 64 * PIT;    // [64 d][PIT]
    float* Vs = Kt + 64 * PIT;    // [64 row][PIT]
    float* Ps = Vs + 64 * PIT;    // [64][64]

    const int tid = threadIdx.x;
    const int bh  = blockIdx.y;
    const int b   = bh >> 4;
    const int h   = bh & 15;
    const int q0  = blockIdx.x * 64;

    const float* qg = g_q + ((size_t)bh * SS + q0) * DKK;
    const float* kg = g_k + (size_t)bh * SS * DKK;
    const float* vg = g_v + (size_t)bh * SS * DKK;

#pragma unroll
    for (int u = 0; u < 4; u++) {
        int off = tid + u * 256;
        float4 qv = *(const float4*)(qg + (size_t)off * 4);
        int row = off >> 4;
        int col = (off & 15) * 4;
        Qt[(col + 0) * PIT + row] = qv.x;
        Qt[(col + 1) * PIT + row] = qv.y;
        Qt[(col + 2) * PIT + row] = qv.z;
        Qt[(col + 3) * PIT + row] = qv.w;
    }

    const int ty = tid >> 4, tx = tid & 15;
    float m_i[4], l_i[4], acc[4][4];
#pragma unroll
    for (int r = 0; r < 4; r++) {
        m_i[r] = -1e30f;
        l_i[r] = 0.f;
#pragma unroll
        for (int j = 0; j < 4; j++) acc[r][j] = 0.f;
    }

    for (int kt = 0; kt < SS; kt += 64) {
        __syncthreads();
#pragma unroll
        for (int u = 0; u < 4; u++) {
            int off = tid + u * 256;
            int row = off >> 4;
            int col = (off & 15) * 4;
            float4 kv = *(const float4*)(kg + (size_t)kt * DKK + (size_t)off * 4);
            Kt[(col + 0) * PIT + row] = kv.x;
            Kt[(col + 1) * PIT + row] = kv.y;
            Kt[(col + 2) * PIT + row] = kv.z;
            Kt[(col + 3) * PIT + row] = kv.w;
            float4 vv = *(const float4*)(vg + (size_t)kt * DKK + (size_t)off * 4);
            *(float4*)&Vs[row * PIT + col] = vv;
        }
        __syncthreads();

        float s[4][4];
#pragma unroll
        for (int r = 0; r < 4; r++)
#pragma unroll
            for (int c = 0; c < 4; c++) s[r][c] = 0.f;

#pragma unroll 16
        for (int d = 0; d < DKK; d++) {
            float4 q4 = *(const float4*)&Qt[d * PIT + ty * 4];
            float4 k4 = *(const float4*)&Kt[d * PIT + tx * 4];
            float qa[4] = {q4.x, q4.y, q4.z, q4.w};
            float ka[4] = {k4.x, k4.y, k4.z, k4.w};
#pragma unroll
            for (int r = 0; r < 4; r++)
#pragma unroll
                for (int c = 0; c < 4; c++) s[r][c] += qa[r] * ka[c];
        }

        const int* mptr = mask + ((size_t)b * SS + (q0 + ty * 4)) * SS + kt + tx * 4;
#pragma unroll
        for (int r = 0; r < 4; r++)
#pragma unroll
            for (int c = 0; c < 4; c++) {
                int mv = __ldg(mptr + (size_t)r * SS + c);
                s[r][c] = mv ? s[r][c] * 0.125f : -1e9f;
            }

#pragma unroll
        for (int r = 0; r < 4; r++) {
            float mx = fmaxf(fmaxf(s[r][0], s[r][1]), fmaxf(s[r][2], s[r][3]));
#pragma unroll
            for (int o = 8; o > 0; o >>= 1)
                mx = fmaxf(mx, __shfl_xor_sync(0xffffffffu, mx, o, 16));
            float mnew = fmaxf(m_i[r], mx);
            float corr = __expf(m_i[r] - mnew);
            m_i[r] = mnew;
            float p0 = __expf(s[r][0] - mnew);
            float p1 = __expf(s[r][1] - mnew);
            float p2 = __expf(s[r][2] - mnew);
            float p3 = __expf(s[r][3] - mnew);
            *(float4*)&Ps[(ty * 4 + r) * 64 + tx * 4] = make_float4(p0, p1, p2, p3);
            float rs = p0 + p1 + p2 + p3;
#pragma unroll
            for (int o = 8; o > 0; o >>= 1)
                rs += __shfl_xor_sync(0xffffffffu, rs, o, 16);
            l_i[r] = l_i[r] * corr + rs;
#pragma unroll
            for (int j = 0; j < 4; j++) acc[r][j] *= corr;
        }
        __syncthreads();

#pragma unroll 4
        for (int c = 0; c < 64; c += 4) {
            float4 v0 = *(const float4*)&Vs[(c + 0) * PIT + tx * 4];
            float4 v1 = *(const float4*)&Vs[(c + 1) * PIT + tx * 4];
            float4 v2 = *(const float4*)&Vs[(c + 2) * PIT + tx * 4];
            float4 v3 = *(const float4*)&Vs[(c + 3) * PIT + tx * 4];
#pragma unroll
            for (int r = 0; r < 4; r++) {
                float4 p4 = *(const float4*)&Ps[(ty * 4 + r) * 64 + c];
                acc[r][0] += p4.x * v0.x + p4.y * v1.x + p4.z * v2.x + p4.w * v3.x;
                acc[r][1] += p4.x * v0.y + p4.y * v1.y + p4.z * v2.y + p4.w * v3.y;
                acc[r][2] += p4.x * v0.z + p4.y * v1.z + p4.z * v2.z + p4.w * v3.z;
                acc[r][3] += p4.x * v0.w + p4.y * v1.w + p4.z * v2.w + p4.w * v3.w;
            }
        }
    }

#pragma unroll
    for (int r = 0; r < 4; r++) {
        float inv = 1.f / l_i[r];
        float4 o = make_float4(acc[r][0] * inv, acc[r][1] * inv,
                               acc[r][2] * inv, acc[r][3] * inv);
        size_t dst = ((size_t)(b * SS + q0 + ty * 4 + r)) * DD + h * 64 + tx * 4;
        *(float4*)&g_x[dst] = o;
    }
}

// ---------------------------------------------------------------------------
extern "C" void kernel_launch(void* const* d_in, const int* in_sizes, int n_in,
                              void* d_out, int out_size) {
    const float* query = (const float*)d_in[0];
    const float* key   = (const float*)d_in[1];
    const float* value = (const float*)d_in[2];
    const int*   mask  = (const int*)d_in[3];
    const float* wq = (const float*)d_in[4];
    const float* bq = (const float*)d_in[5];
    const float* wk = (const float*)d_in[6];
    const float* bk = (const float*)d_in[7];
    const float* wv = (const float*)d_in[8];
    const float* bv = (const float*)d_in[9];
    const float* wo = (const float*)d_in[10];
    const float* bo = (const float*)d_in[11];
    float* out = (float*)d_out;

    static int smem_ok = 0;
    const int attn_smem = (3 * 64 * PIT + 64 * 64) * (int)sizeof(float);  // 68608 B
    if (!smem_ok) {
        cudaFuncSetAttribute(attn_kernel, cudaFuncAttributeMaxDynamicSharedMemorySize,
                             attn_smem);
        smem_ok = 1;
    }

    dim3 ggrid(DD / 128, (BB * SS) / 128);  // (8, 32)
    gemm_tc<0><<<ggrid, 256>>>(query, wq, bq, nullptr);
    gemm_tc<1><<<ggrid, 256>>>(key,   wk, bk, nullptr);
    gemm_tc<2><<<ggrid, 256>>>(value, wv, bv, nullptr);

    attn_kernel<<<dim3(SS / 64, BB * HH), 256, attn_smem>>>(mask);

    gemm_tc<3><<<ggrid, 256>>>(nullptr, wo, bo, out);
}

// round 6
// speedup vs baseline: 1.9580x; 1.3961x over previous
#include <cuda_runtime.h>
#include <math.h>
#include <stdint.h>

#define BB 4
#define SS 1024
#define DD 1024
#define HH 16
#define DKK 64

// Scratch (no allocations allowed).
__device__ float g_q[BB * HH * SS * DKK];
__device__ float g_k[BB * HH * SS * DKK];
__device__ float g_v[BB * HH * SS * DKK];
__device__ float g_x[BB * SS * DD];
__device__ uint32_t g_mbits[BB * SS * (SS / 32)];

__device__ __forceinline__ uint32_t f2tf32(float x) {
    uint32_t r;
    asm("cvt.rna.tf32.f32 %0, %1;" : "=r"(r) : "f"(x));
    return r;
}

__device__ __forceinline__ void mma_tf32(float& c0, float& c1, float& c2, float& c3,
                                         uint32_t a0, uint32_t a1, uint32_t a2, uint32_t a3,
                                         uint32_t b0, uint32_t b1) {
    asm volatile(
        "mma.sync.aligned.m16n8k8.row.col.f32.tf32.tf32.f32 "
        "{%0,%1,%2,%3}, {%4,%5,%6,%7}, {%8,%9}, {%0,%1,%2,%3};"
        : "+f"(c0), "+f"(c1), "+f"(c2), "+f"(c3)
        : "r"(a0), "r"(a1), "r"(a2), "r"(a3), "r"(b0), "r"(b1));
}

// ---------------------------------------------------------------------------
// NT tensor-core GEMM (tf32) — unchanged from R5 (validated).
// ---------------------------------------------------------------------------
#define GPAD 20

template <int DST>
__global__ __launch_bounds__(256) void gemm_tc(const float* __restrict__ A,
                                               const float* __restrict__ W,
                                               const float* __restrict__ bias,
                                               float* __restrict__ C) {
    __shared__ uint32_t As[2][128 * GPAD];
    __shared__ uint32_t Bs[2][128 * GPAD];

    const int tid  = threadIdx.x;
    const int lane = tid & 31;
    const int warp = tid >> 5;
    const int wm   = warp >> 2;
    const int wn   = warp & 3;
    const int g    = lane >> 2;
    const int t    = lane & 3;
    const int m0 = blockIdx.y * 128;
    const int n0 = blockIdx.x * 128;

    if (DST == 3) A = g_x;

    const int lrow  = tid >> 1;
    const int khalf = (tid & 1) * 8;
    const float* Ap = A + (size_t)(m0 + lrow) * DD + khalf;
    const float* Wp = W + (size_t)(n0 + lrow) * DD + khalf;
    const int sbase = lrow * GPAD + khalf;

    float acc[4][4][4];
#pragma unroll
    for (int i = 0; i < 4; i++)
#pragma unroll
        for (int j = 0; j < 4; j++)
#pragma unroll
            for (int c = 0; c < 4; c++) acc[i][j][c] = 0.f;

    float4 ra0 = *(const float4*)(Ap);
    float4 ra1 = *(const float4*)(Ap + 4);
    float4 rb0 = *(const float4*)(Wp);
    float4 rb1 = *(const float4*)(Wp + 4);

    auto sts_tile = [&](uint32_t* SA, uint32_t* SB,
                        float4 a0, float4 a1, float4 b0, float4 b1) {
        SA[sbase + 0] = f2tf32(a0.x); SA[sbase + 2] = f2tf32(a0.y);
        SA[sbase + 4] = f2tf32(a0.z); SA[sbase + 6] = f2tf32(a0.w);
        SA[sbase + 1] = f2tf32(a1.x); SA[sbase + 3] = f2tf32(a1.y);
        SA[sbase + 5] = f2tf32(a1.z); SA[sbase + 7] = f2tf32(a1.w);
        SB[sbase + 0] = f2tf32(b0.x); SB[sbase + 2] = f2tf32(b0.y);
        SB[sbase + 4] = f2tf32(b0.z); SB[sbase + 6] = f2tf32(b0.w);
        SB[sbase + 1] = f2tf32(b1.x); SB[sbase + 3] = f2tf32(b1.y);
        SB[sbase + 5] = f2tf32(b1.z); SB[sbase + 7] = f2tf32(b1.w);
    };

    sts_tile(As[0], Bs[0], ra0, ra1, rb0, rb1);
    __syncthreads();

    int cur = 0;
    const int NTILES = DD / 16;
    for (int it = 0; it < NTILES; ++it) {
        if (it + 1 < NTILES) {
            const float* ap = Ap + (it + 1) * 16;
            const float* wp = Wp + (it + 1) * 16;
            ra0 = *(const float4*)(ap);
            ra1 = *(const float4*)(ap + 4);
            rb0 = *(const float4*)(wp);
            rb1 = *(const float4*)(wp + 4);
        }

        const uint32_t* SA = As[cur];
        const uint32_t* SB = Bs[cur];
#pragma unroll
        for (int s = 0; s < 2; s++) {
            uint32_t a[4][4];
#pragma unroll
            for (int mi = 0; mi < 4; mi++) {
                const int r0 = wm * 64 + mi * 16 + g;
                uint2 p0 = *(const uint2*)&SA[r0 * GPAD + s * 8 + 2 * t];
                uint2 p1 = *(const uint2*)&SA[(r0 + 8) * GPAD + s * 8 + 2 * t];
                a[mi][0] = p0.x; a[mi][1] = p1.x; a[mi][2] = p0.y; a[mi][3] = p1.y;
            }
            uint32_t b[4][2];
#pragma unroll
            for (int nj = 0; nj < 4; nj++) {
                uint2 q = *(const uint2*)&SB[(wn * 32 + nj * 8 + g) * GPAD + s * 8 + 2 * t];
                b[nj][0] = q.x; b[nj][1] = q.y;
            }
#pragma unroll
            for (int mi = 0; mi < 4; mi++)
#pragma unroll
                for (int nj = 0; nj < 4; nj++)
                    mma_tf32(acc[mi][nj][0], acc[mi][nj][1], acc[mi][nj][2], acc[mi][nj][3],
                             a[mi][0], a[mi][1], a[mi][2], a[mi][3],
                             b[nj][0], b[nj][1]);
        }

        if (it + 1 < NTILES) {
            sts_tile(As[cur ^ 1], Bs[cur ^ 1], ra0, ra1, rb0, rb1);
            __syncthreads();
            cur ^= 1;
        }
    }

#pragma unroll
    for (int mi = 0; mi < 4; mi++) {
#pragma unroll
        for (int nj = 0; nj < 4; nj++) {
            const int n = n0 + wn * 32 + nj * 8 + 2 * t;
            const float bn0 = __ldg(&bias[n]);
            const float bn1 = __ldg(&bias[n + 1]);
#pragma unroll
            for (int rr = 0; rr < 2; rr++) {
                const int m = m0 + wm * 64 + mi * 16 + g + rr * 8;
                const float v0 = acc[mi][nj][rr * 2 + 0] + bn0;
                const float v1 = acc[mi][nj][rr * 2 + 1] + bn1;
                if (DST == 3) {
                    *(float2*)&C[(size_t)m * DD + n] = make_float2(v0, v1);
                } else {
                    const int bb = m >> 10;
                    const int s  = m & (SS - 1);
                    const int h  = n >> 6;
                    const int dk = n & (DKK - 1);
                    float* dst = (DST == 0) ? g_q : (DST == 1) ? g_k : g_v;
                    *(float2*)&dst[(((size_t)(bb * HH + h)) * SS + s) * DKK + dk] =
                        make_float2(v0, v1);
                }
            }
        }
    }
}

// ---------------------------------------------------------------------------
// Mask bit-pack: one warp packs 32 ints -> 1 uint32 via ballot.
// ---------------------------------------------------------------------------
__global__ __launch_bounds__(256) void pack_mask(const int* __restrict__ mask) {
    const int gid = blockIdx.x * 256 + threadIdx.x;   // < BB*SS*SS
    const int v = mask[gid] != 0;
    const uint32_t bits = __ballot_sync(0xffffffffu, v);
    if ((threadIdx.x & 31) == 0) g_mbits[gid >> 5] = bits;
}

// ---------------------------------------------------------------------------
// Tensor-core flash attention. Grid (S/64, B*H), 128 thr = 4 warps.
// Each warp owns 16 q-rows. All tiles stored in SMEM as tf32 bits with the
// same k-pair interleave as gemm_tc (pos = 2*(k%4) + k/4 within each 8-group).
// Pitch 72 words (bank-clean for all fragment loads).
// ---------------------------------------------------------------------------
#define ATP 72

__global__ __launch_bounds__(128) void attn_tc() {
    extern __shared__ uint32_t smu[];
    uint32_t* Qs = smu;              // [64 q][ATP] d-interleaved
    uint32_t* Ks = Qs + 64 * ATP;    // [64 kk][ATP] d-interleaved
    uint32_t* Vs = Ks + 64 * ATP;    // [64 kk][ATP] d-interleaved
    uint32_t* Ps = Vs + 64 * ATP;    // [64 q][ATP] kk-interleaved

    const int tid  = threadIdx.x;
    const int lane = tid & 31;
    const int warp = tid >> 5;       // 0..3
    const int g = lane >> 2;         // 0..7
    const int t = lane & 3;          // 0..3
    const int bh = blockIdx.y;
    const int b = bh >> 4, h = bh & 15;
    const int q0 = blockIdx.x * 64;

    const float* qg = g_q + ((size_t)bh * SS + q0) * DKK;
    const float* kg = g_k + (size_t)bh * SS * DKK;
    const float* vg = g_v + (size_t)bh * SS * DKK;

    // Load Q tile -> tf32 SMEM, d-interleaved.
#pragma unroll
    for (int u = 0; u < 8; u++) {
        const int off = tid + u * 128;            // float4 index, 1024 total
        float4 qv = *(const float4*)(qg + (size_t)off * 4);
        const int row = off >> 4;
        const int d0  = (off & 15) * 4;
        const int base = row * ATP + (d0 >> 3) * 8 + ((d0 & 7) ? 1 : 0);
        Qs[base + 0] = f2tf32(qv.x); Qs[base + 2] = f2tf32(qv.y);
        Qs[base + 4] = f2tf32(qv.z); Qs[base + 6] = f2tf32(qv.w);
    }
    __syncthreads();

    // Q fragments live in registers for the whole kernel.
    uint32_t aq[8][4];
#pragma unroll
    for (int ks = 0; ks < 8; ks++) {
        uint2 p0 = *(const uint2*)&Qs[(warp * 16 + g) * ATP + ks * 8 + 2 * t];
        uint2 p1 = *(const uint2*)&Qs[(warp * 16 + g + 8) * ATP + ks * 8 + 2 * t];
        aq[ks][0] = p0.x; aq[ks][1] = p1.x; aq[ks][2] = p0.y; aq[ks][3] = p1.y;
    }

    float o[8][4];
#pragma unroll
    for (int nj = 0; nj < 8; nj++)
#pragma unroll
        for (int c = 0; c < 4; c++) o[nj][c] = 0.f;
    float m0 = -1e30f, m1 = -1e30f, l0 = 0.f, l1 = 0.f;

    const uint32_t* mrow = g_mbits + ((size_t)b * SS + (q0 + warp * 16 + g)) * (SS / 32);
    const int ig = 2 * (g & 3) + (g >> 2);   // interleaved pos of d-local = g

    for (int kt = 0; kt < 16; kt++) {
        __syncthreads();
#pragma unroll
        for (int u = 0; u < 8; u++) {
            const int off = tid + u * 128;
            const int row = off >> 4;
            const int d0  = (off & 15) * 4;
            const int base = row * ATP + (d0 >> 3) * 8 + ((d0 & 7) ? 1 : 0);
            float4 kv = *(const float4*)(kg + (size_t)kt * 4096 + (size_t)off * 4);
            Ks[base + 0] = f2tf32(kv.x); Ks[base + 2] = f2tf32(kv.y);
            Ks[base + 4] = f2tf32(kv.z); Ks[base + 6] = f2tf32(kv.w);
            float4 vv = *(const float4*)(vg + (size_t)kt * 4096 + (size_t)off * 4);
            Vs[base + 0] = f2tf32(vv.x); Vs[base + 2] = f2tf32(vv.y);
            Vs[base + 4] = f2tf32(vv.z); Vs[base + 6] = f2tf32(vv.w);
        }
        __syncthreads();

        // S = Q K^T  (16 x 64 per warp)
        float s[8][4];
#pragma unroll
        for (int nj = 0; nj < 8; nj++)
#pragma unroll
            for (int c = 0; c < 4; c++) s[nj][c] = 0.f;
#pragma unroll
        for (int nj = 0; nj < 8; nj++)
#pragma unroll
            for (int ks = 0; ks < 8; ks++) {
                uint2 kb = *(const uint2*)&Ks[(nj * 8 + g) * ATP + ks * 8 + 2 * t];
                mma_tf32(s[nj][0], s[nj][1], s[nj][2], s[nj][3],
                         aq[ks][0], aq[ks][1], aq[ks][2], aq[ks][3], kb.x, kb.y);
            }

        // Mask + scale (bit-packed mask, 4 words per thread per k-tile).
        const uint32_t w0lo = mrow[kt * 2];
        const uint32_t w0hi = mrow[kt * 2 + 1];
        const uint32_t w1lo = mrow[8 * (SS / 32) + kt * 2];
        const uint32_t w1hi = mrow[8 * (SS / 32) + kt * 2 + 1];
#pragma unroll
        for (int nj = 0; nj < 8; nj++) {
            const uint32_t wr0 = (nj < 4) ? w0lo : w0hi;
            const uint32_t wr1 = (nj < 4) ? w1lo : w1hi;
            const int sh = (nj & 3) * 8 + 2 * t;
            s[nj][0] = ((wr0 >> sh) & 1u)       ? s[nj][0] * 0.125f : -1e9f;
            s[nj][1] = ((wr0 >> (sh + 1)) & 1u) ? s[nj][1] * 0.125f : -1e9f;
            s[nj][2] = ((wr1 >> sh) & 1u)       ? s[nj][2] * 0.125f : -1e9f;
            s[nj][3] = ((wr1 >> (sh + 1)) & 1u) ? s[nj][3] * 0.125f : -1e9f;
        }

        // Online softmax (rows g and g+8; quad = lanes sharing a row).
        float mx0 = -1e30f, mx1 = -1e30f;
#pragma unroll
        for (int nj = 0; nj < 8; nj++) {
            mx0 = fmaxf(mx0, fmaxf(s[nj][0], s[nj][1]));
            mx1 = fmaxf(mx1, fmaxf(s[nj][2], s[nj][3]));
        }
        mx0 = fmaxf(mx0, __shfl_xor_sync(0xffffffffu, mx0, 1));
        mx0 = fmaxf(mx0, __shfl_xor_sync(0xffffffffu, mx0, 2));
        mx1 = fmaxf(mx1, __shfl_xor_sync(0xffffffffu, mx1, 1));
        mx1 = fmaxf(mx1, __shfl_xor_sync(0xffffffffu, mx1, 2));
        const float mn0 = fmaxf(m0, mx0), mn1 = fmaxf(m1, mx1);
        const float cr0 = __expf(m0 - mn0), cr1 = __expf(m1 - mn1);
        m0 = mn0; m1 = mn1;

        const int pa = 2 * ((2 * t) & 3) + ((2 * t) >> 2);
        const int pb = 2 * ((2 * t + 1) & 3) + ((2 * t + 1) >> 2);
        float rs0 = 0.f, rs1 = 0.f;
#pragma unroll
        for (int nj = 0; nj < 8; nj++) {
            const float p0 = __uint_as_float(f2tf32(__expf(s[nj][0] - m0)));
            const float p1 = __uint_as_float(f2tf32(__expf(s[nj][1] - m0)));
            const float p2 = __uint_as_float(f2tf32(__expf(s[nj][2] - m1)));
            const float p3 = __uint_as_float(f2tf32(__expf(s[nj][3] - m1)));
            rs0 += p0 + p1;
            rs1 += p2 + p3;
            const int pb0 = (warp * 16 + g) * ATP + nj * 8;
            const int pb1 = (warp * 16 + g + 8) * ATP + nj * 8;
            Ps[pb0 + pa] = __float_as_uint(p0);
            Ps[pb0 + pb] = __float_as_uint(p1);
            Ps[pb1 + pa] = __float_as_uint(p2);
            Ps[pb1 + pb] = __float_as_uint(p3);
        }
        rs0 += __shfl_xor_sync(0xffffffffu, rs0, 1);
        rs0 += __shfl_xor_sync(0xffffffffu, rs0, 2);
        rs1 += __shfl_xor_sync(0xffffffffu, rs1, 1);
        rs1 += __shfl_xor_sync(0xffffffffu, rs1, 2);
        l0 = l0 * cr0 + rs0;
        l1 = l1 * cr1 + rs1;
#pragma unroll
        for (int nj = 0; nj < 8; nj++) {
            o[nj][0] *= cr0; o[nj][1] *= cr0;
            o[nj][2] *= cr1; o[nj][3] *= cr1;
        }
        __syncwarp();

        // O += P V
#pragma unroll
        for (int ks = 0; ks < 8; ks++) {
            uint2 p0 = *(const uint2*)&Ps[(warp * 16 + g) * ATP + ks * 8 + 2 * t];
            uint2 p1 = *(const uint2*)&Ps[(warp * 16 + g + 8) * ATP + ks * 8 + 2 * t];
#pragma unroll
            for (int nj = 0; nj < 8; nj++) {
                const uint32_t b0 = Vs[(ks * 8 + t) * ATP + nj * 8 + ig];
                const uint32_t b1 = Vs[(ks * 8 + t + 4) * ATP + nj * 8 + ig];
                mma_tf32(o[nj][0], o[nj][1], o[nj][2], o[nj][3],
                         p0.x, p1.x, p0.y, p1.y, b0, b1);
            }
        }
        __syncwarp();
    }

    // Epilogue: normalize, write [B,S,D].
    const float i0 = 1.f / l0, i1 = 1.f / l1;
    const size_t r0 = ((size_t)(b * SS + q0 + warp * 16 + g)) * DD + h * 64;
    const size_t r1 = r0 + (size_t)8 * DD;
#pragma unroll
    for (int nj = 0; nj < 8; nj++) {
        *(float2*)&g_x[r0 + nj * 8 + 2 * t] = make_float2(o[nj][0] * i0, o[nj][1] * i0);
        *(float2*)&g_x[r1 + nj * 8 + 2 * t] = make_float2(o[nj][2] * i1, o[nj][3] * i1);
    }
}

// ---------------------------------------------------------------------------
extern "C" void kernel_launch(void* const* d_in, const int* in_sizes, int n_in,
                              void* d_out, int out_size) {
    const float* query = (const float*)d_in[0];
    const float* key   = (const float*)d_in[1];
    const float* value = (const float*)d_in[2];
    const int*   mask  = (const int*)d_in[3];
    const float* wq = (const float*)d_in[4];
    const float* bq = (const float*)d_in[5];
    const float* wk = (const float*)d_in[6];
    const float* bk = (const float*)d_in[7];
    const float* wv = (const float*)d_in[8];
    const float* bv = (const float*)d_in[9];
    const float* wo = (const float*)d_in[10];
    const float* bo = (const float*)d_in[11];
    float* out = (float*)d_out;

    static int smem_ok = 0;
    const int attn_smem = 4 * 64 * ATP * (int)sizeof(uint32_t);  // 73728 B
    if (!smem_ok) {
        cudaFuncSetAttribute(attn_tc, cudaFuncAttributeMaxDynamicSharedMemorySize,
                             attn_smem);
        smem_ok = 1;
    }

    pack_mask<<<(BB * SS * SS) / 256, 256>>>(mask);

    dim3 ggrid(DD / 128, (BB * SS) / 128);  // (8, 32)
    gemm_tc<0><<<ggrid, 256>>>(query, wq, bq, nullptr);
    gemm_tc<1><<<ggrid, 256>>>(key,   wk, bk, nullptr);
    gemm_tc<2><<<ggrid, 256>>>(value, wv, bv, nullptr);

    attn_tc<<<dim3(SS / 64, BB * HH), 128, attn_smem>>>();

    gemm_tc<3><<<ggrid, 256>>>(nullptr, wo, bo, out);
}